// round 15
// baseline (speedup 1.0000x reference)
#include <cuda_runtime.h>
#include <stdint.h>
#include <math.h>

#define C64 64
#define HW  3136
#define MTOT 401408            // 128*3136
#define PTILES 98              // 3136/32 position tiles (apply)
#define PT2 49                 // 3136/64 position tiles (gram)
#define NBG 392
#define TPG2 16                // 392*16 = 6272 double-tiles
#define NBA 1568
#define TPA 8
#define NS_ITERS 3
#define EPSV 1e-3f
#define GS 36                  // apply smem tile stride (floats)
#define GS2 68                 // gram smem tile stride (floats, 272B rows)

// -------- device scratch (no allocations allowed) --------
__device__ float g_partG[NBG][C64 * C64];
__device__ float g_partS[NBG][C64];
__device__ float g_G[C64 * C64];
__device__ float g_S[C64];
__device__ float g_wm[C64 * C64];
__device__ float g_bias[C64];

// =============================== helpers ===============================
__device__ __forceinline__ void cpasync16(uint32_t dst, const void* src) {
    asm volatile("cp.async.cg.shared.global [%0], [%1], 16;" :: "r"(dst), "l"(src));
}
__device__ __forceinline__ void cp_commit() {
    asm volatile("cp.async.commit_group;" ::: "memory");
}
__device__ __forceinline__ void cp_wait1() {
    asm volatile("cp.async.wait_group 1;" ::: "memory");
}

// m16n8k8 tf32 HMMA (sm_80+ feature, works on bare sm_103 target).
__device__ __forceinline__ void mma_tf32(float* c, uint32_t a0, uint32_t a1,
                                         uint32_t a2, uint32_t a3,
                                         uint32_t b0, uint32_t b1) {
    asm volatile("mma.sync.aligned.m16n8k8.row.col.f32.tf32.tf32.f32 "
                 "{%0,%1,%2,%3}, {%4,%5,%6,%7}, {%8,%9}, {%0,%1,%2,%3};"
                 : "+f"(c[0]), "+f"(c[1]), "+f"(c[2]), "+f"(c[3])
                 : "r"(a0), "r"(a1), "r"(a2), "r"(a3), "r"(b0), "r"(b1));
}
__device__ __forceinline__ uint32_t ldf(const float* p) {
    return __float_as_uint(*p);
}

// 256-thread tile loader (apply): 64 rows x 32 f32 into [64][GS].
__device__ __forceinline__ void tile_issue(const float* __restrict__ X, int tile,
                                           float* stage, int tid) {
    const int n = tile / PTILES;
    const int s0 = (tile - n * PTILES) * 32;
    const float* base = X + (size_t)n * (C64 * HW) + s0;
    const uint32_t sa = (uint32_t)__cvta_generic_to_shared(stage);
#pragma unroll
    for (int j = 0; j < 2; ++j) {
        const int idx = tid + j * 256;
        const int r = idx >> 3, q = idx & 7;
        cpasync16(sa + (uint32_t)(r * GS * 4 + q * 16), base + (size_t)r * HW + 4 * q);
    }
    cp_commit();
}

// 192-thread double-tile loader (gram): 64 rows x 64 f32 into [64][GS2].
__device__ __forceinline__ void tile_issue_k64(const float* __restrict__ X, int td,
                                               float* stage, int tid) {
    const int n = td / PT2;
    const int s0 = (td - n * PT2) * 64;
    const float* base = X + (size_t)n * (C64 * HW) + s0;
    const uint32_t sa = (uint32_t)__cvta_generic_to_shared(stage);
#pragma unroll
    for (int j = 0; j < 6; ++j) {
        const int idx = tid + j * 192;
        if (idx < 1024) {
            const int r = idx >> 4, q = idx & 15;
            cpasync16(sa + (uint32_t)(r * GS2 * 4 + q * 16), base + (size_t)r * HW + 4 * q);
        }
    }
    cp_commit();
}

// =====================================================================
// Pass 1: tf32 HMMA Gram, symmetric tiling, K=64 per iteration. 192 thr.
// warp tiles (rows,cols): w0(0,0) w1(16,0) w2(32,0) w3(48,0) w4(32,32) w5(48,32)
// Diagonal-block warps {0,1,4,5} reuse B-fragment registers as A.
// Offdiag warps {2,3} also write transposed mirror.
// 3-stage cp.async, wait->issue->compute (apply-proven ordering).
// =====================================================================
__global__ void __launch_bounds__(192) gram_kernel(const float* __restrict__ X) {
    __shared__ float stg[3][64 * GS2];
    __shared__ float ssc[3][64];

    const int tid = threadIdx.x;
    const int wid = tid >> 5, lane = tid & 31;
    const int la2 = lane >> 2, la3 = lane & 3;
    const int rb = (wid < 4) ? wid * 16 : (wid - 4) * 16 + 32;
    const int cb = (wid < 4) ? 0 : 32;
    const int sch = tid & 63, seg = tid >> 6;       // seg 0..2
    const int nf4 = (seg == 0) ? 6 : 5;             // 6+5+5 = 16 f4 per row
    const int f4b = (seg == 0) ? 0 : 6 + (seg - 1) * 5;

    float acc[4][4];
#pragma unroll
    for (int i = 0; i < 4; ++i)
#pragma unroll
        for (int j = 0; j < 4; ++j) acc[i][j] = 0.f;
    float ssum = 0.f;

    const int tile0 = blockIdx.x * TPG2;
    tile_issue_k64(X, tile0 + 0, stg[0], tid);
    tile_issue_k64(X, tile0 + 1, stg[1], tid);

#pragma unroll 1
    for (int t = 0; t < TPG2; ++t) {
        cp_wait1();
        __syncthreads();
        if (t + 2 < TPG2) tile_issue_k64(X, tile0 + t + 2, stg[(t + 2) % 3], tid);
        else cp_commit();   // keep group accounting consistent

        const float* S = stg[t % 3];

        // channel sums: thread covers (ch, f4 range)
#pragma unroll
        for (int j = 0; j < 6; ++j) {
            if (j < nf4) {
                const float4 u = *reinterpret_cast<const float4*>(S + sch * GS2 + (f4b + j) * 4);
                ssum += (u.x + u.y) + (u.z + u.w);
            }
        }

#pragma unroll
        for (int kk = 0; kk < 8; ++kk) {
            const int k0 = kk * 8;
            uint32_t B0[4], B1[4];
#pragma unroll
            for (int nt = 0; nt < 4; ++nt) {
                B0[nt] = ldf(S + (cb + nt * 8 + la2) * GS2 + k0 + la3);
                B1[nt] = ldf(S + (cb + nt * 8 + la2) * GS2 + k0 + 4 + la3);
            }
            uint32_t a0, a1, a2, a3;
            if (wid == 0 || wid == 4)      { a0 = B0[0]; a1 = B0[1]; a2 = B1[0]; a3 = B1[1]; }
            else if (wid == 1 || wid == 5) { a0 = B0[2]; a1 = B0[3]; a2 = B1[2]; a3 = B1[3]; }
            else {
                a0 = ldf(S + (rb + la2) * GS2 + k0 + la3);
                a1 = ldf(S + (rb + 8 + la2) * GS2 + k0 + la3);
                a2 = ldf(S + (rb + la2) * GS2 + k0 + 4 + la3);
                a3 = ldf(S + (rb + 8 + la2) * GS2 + k0 + 4 + la3);
            }
#pragma unroll
            for (int nt = 0; nt < 4; ++nt)
                mma_tf32(acc[nt], a0, a1, a2, a3, B0[nt], B1[nt]);
        }
        __syncthreads();
    }

    // write partial G (block + mirror for offdiag warps)
    float* pg = g_partG[blockIdx.x];
    const int r0 = rb + la2;
#pragma unroll
    for (int nt = 0; nt < 4; ++nt) {
        const int c0 = cb + nt * 8 + la3 * 2;
        *reinterpret_cast<float2*>(pg + r0 * C64 + c0) = make_float2(acc[nt][0], acc[nt][1]);
        *reinterpret_cast<float2*>(pg + (r0 + 8) * C64 + c0) = make_float2(acc[nt][2], acc[nt][3]);
        if (wid == 2 || wid == 3) {
            pg[c0 * C64 + r0] = acc[nt][0];
            pg[(c0 + 1) * C64 + r0] = acc[nt][1];
            pg[c0 * C64 + r0 + 8] = acc[nt][2];
            pg[(c0 + 1) * C64 + r0 + 8] = acc[nt][3];
        }
    }
    // reduce channel sums
    ssc[seg][sch] = ssum;
    __syncthreads();
    if (tid < 64)
        g_partS[blockIdx.x][tid] = ssc[0][tid] + ssc[1][tid] + ssc[2][tid];
}

// =====================================================================
// Pass 1.5: reduce partials (fixed order -> deterministic)
// =====================================================================
__global__ void __launch_bounds__(128) reduce_kernel() {
    const int tid = threadIdx.x;
    if (blockIdx.x < 128) {
        __shared__ float4 s[8][8];
        if (tid < 64) {
            const int lane = tid & 7, g = tid >> 3;
            const int e4 = blockIdx.x * 8 + lane;
            const float4* pg = reinterpret_cast<const float4*>(g_partG);
            float4 a = make_float4(0.f, 0.f, 0.f, 0.f);
            const int b0 = g * (NBG / 8);
#pragma unroll 7
            for (int b = 0; b < NBG / 8; ++b) {
                const float4 t = pg[(size_t)(b0 + b) * 1024 + e4];
                a.x += t.x; a.y += t.y; a.z += t.z; a.w += t.w;
            }
            s[g][lane] = a;
        }
        __syncthreads();
        if (tid < 8) {
            float4 r = make_float4(0.f, 0.f, 0.f, 0.f);
            for (int i = 0; i < 8; ++i) {
                const float4 t = s[i][tid];
                r.x += t.x; r.y += t.y; r.z += t.z; r.w += t.w;
            }
            reinterpret_cast<float4*>(g_G)[blockIdx.x * 8 + tid] = r;
        }
    } else {
        __shared__ float s2[2][64];
        const int ch = tid & 63, half = tid >> 6;
        float a = 0.f;
        const int b0 = half * (NBG / 2);
#pragma unroll 4
        for (int b = 0; b < NBG / 2; ++b) a += g_partS[b0 + b][ch];
        s2[half][ch] = a;
        __syncthreads();
        if (tid < 64) g_S[tid] = s2[0][tid] + s2[1][tid];
    }
}

// =====================================================================
// Pass 2: single-block Newton-Schulz inverse sqrt (fp32, FFMA2), 256 thr
// =====================================================================
__device__ __forceinline__ uint64_t pack2(float v) {
    uint64_t r; asm("mov.b64 %0, {%1, %1};" : "=l"(r) : "f"(v)); return r;
}
__device__ __forceinline__ void ffma2(uint64_t& d, uint64_t a, uint64_t b) {
    asm("fma.rn.f32x2 %0, %1, %2, %0;" : "+l"(d) : "l"(a), "l"(b));
}
__device__ __forceinline__ float2 unpack2(uint64_t v) {
    float2 f; asm("mov.b64 {%0, %1}, %2;" : "=f"(f.x), "=f"(f.y) : "l"(v)); return f;
}

__device__ __forceinline__ void mm64_2(const float (*P)[68], const float (*Q)[68],
                                       float (*Cm)[68], int ty, int tx) {
    uint64_t acc[2][4];
#pragma unroll
    for (int i = 0; i < 2; ++i)
#pragma unroll
        for (int j = 0; j < 4; ++j) acc[i][j] = 0ull;
#pragma unroll 8
    for (int k = 0; k < 64; ++k) {
        const ulonglong2 a = *reinterpret_cast<const ulonglong2*>(&P[k][ty * 4]);
        const float4 b = *reinterpret_cast<const float4*>(&Q[k][tx * 4]);
        const uint64_t bd[4] = {pack2(b.x), pack2(b.y), pack2(b.z), pack2(b.w)};
#pragma unroll
        for (int j = 0; j < 4; ++j) { ffma2(acc[0][j], a.x, bd[j]); ffma2(acc[1][j], a.y, bd[j]); }
    }
#pragma unroll
    for (int i = 0; i < 2; ++i) {
        const float2 u0 = unpack2(acc[i][0]), u1 = unpack2(acc[i][1]);
        const float2 u2 = unpack2(acc[i][2]), u3 = unpack2(acc[i][3]);
        const int rowA = ty * 4 + 2 * i, rowB = rowA + 1;
        Cm[rowA][tx * 4 + 0] = u0.x; Cm[rowA][tx * 4 + 1] = u1.x;
        Cm[rowA][tx * 4 + 2] = u2.x; Cm[rowA][tx * 4 + 3] = u3.x;
        Cm[rowB][tx * 4 + 0] = u0.y; Cm[rowB][tx * 4 + 1] = u1.y;
        Cm[rowB][tx * 4 + 2] = u2.y; Cm[rowB][tx * 4 + 3] = u3.y;
    }
}

__global__ void __launch_bounds__(256) solve_kernel() {
    extern __shared__ float smf[];
    float (*An)[68] = (float(*)[68])smf;
    float (*Z)[68]  = (float(*)[68])(smf + 1 * 64 * 68);
    float (*B1)[68] = (float(*)[68])(smf + 2 * 64 * 68);
    float (*B2)[68] = (float(*)[68])(smf + 3 * 64 * 68);
    __shared__ float rowsum[64];
    __shared__ float rinv;

    const int tid = threadIdx.x;
    const int ty = tid >> 4, tx = tid & 15;
    const float invm = 1.f / (float)MTOT;

    for (int e = tid; e < 4096; e += 256) {
        const int i = e >> 6, j = e & 63;
        float s = g_G[e] * invm - (g_S[i] * invm) * (g_S[j] * invm);
        if (i == j) s += EPSV;
        An[i][j] = s;
        Z[i][j] = (i == j) ? 1.f : 0.f;
    }
    __syncthreads();
    if (tid < 64) {
        float rs = 0.f;
        for (int j = 0; j < 64; ++j) rs += fabsf(An[tid][j]);
        rowsum[tid] = rs;
    }
    __syncthreads();
    if (tid == 0) {
        float mx = 0.f;
        for (int i = 0; i < 64; ++i) mx = fmaxf(mx, rowsum[i]);
        rinv = 1.f / mx;
    }
    __syncthreads();
    const float r = rinv;
    for (int e = tid; e < 4096; e += 256) An[e >> 6][e & 63] *= r;
    __syncthreads();

    for (int it = 0; it < NS_ITERS; ++it) {
        mm64_2(Z, Z, B1, ty, tx);
        __syncthreads();
        mm64_2(B1, Z, B2, ty, tx);
        __syncthreads();
        {
            uint64_t acc[2][4];
#pragma unroll
            for (int i = 0; i < 2; ++i)
#pragma unroll
                for (int j = 0; j < 4; ++j) acc[i][j] = 0ull;
#pragma unroll 8
            for (int k = 0; k < 64; ++k) {
                const ulonglong2 a = *reinterpret_cast<const ulonglong2*>(&An[k][ty * 4]);
                const float4 b = *reinterpret_cast<const float4*>(&B2[k][tx * 4]);
                const uint64_t bd[4] = {pack2(b.x), pack2(b.y), pack2(b.z), pack2(b.w)};
#pragma unroll
                for (int j = 0; j < 4; ++j) { ffma2(acc[0][j], a.x, bd[j]); ffma2(acc[1][j], a.y, bd[j]); }
            }
#pragma unroll
            for (int i = 0; i < 2; ++i) {
                const float2 u[4] = {unpack2(acc[i][0]), unpack2(acc[i][1]),
                                     unpack2(acc[i][2]), unpack2(acc[i][3])};
                const int rowA = ty * 4 + 2 * i, rowB = rowA + 1;
#pragma unroll
                for (int j = 0; j < 4; ++j) {
                    Z[rowA][tx * 4 + j] = 1.5f * Z[rowA][tx * 4 + j] - 0.5f * u[j].x;
                    Z[rowB][tx * 4 + j] = 1.5f * Z[rowB][tx * 4 + j] - 0.5f * u[j].y;
                }
            }
        }
        __syncthreads();
    }

    const float sr = sqrtf(r);
    for (int e = tid; e < 4096; e += 256) g_wm[e] = Z[e >> 6][e & 63] * sr;
    __syncthreads();
    if (tid < 64) {
        float b = 0.f;
        for (int k = 0; k < 64; ++k) b += Z[tid][k] * g_S[k];
        g_bias[tid] = b * sr * invm;
    }
}

// =====================================================================
// Pass 3: tf32 HMMA apply (R14-measured 47.1us). 32x8 warp tiles,
// A fragments hoisted (64 regs); direct fragment stores.
// dyn smem: Wm[64][68] | 3 stages [64][GS] | bias[64]
// =====================================================================
__global__ void __launch_bounds__(256) apply_kernel(const float* __restrict__ X,
                                                    float* __restrict__ Y) {
    extern __shared__ float sm[];
    float (*Wm)[68] = (float(*)[68])sm;                 // 4352 floats
    float* stages = sm + 4352;                          // 3 * 2304
    float* bs = sm + 4352 + 3 * 64 * GS;

    const int tid = threadIdx.x;
    const int wid = tid >> 5, lane = tid & 31;
    const int la2 = lane >> 2, la3 = lane & 3;
    const int rb = (wid & 1) * 32, cbw = (wid >> 1) * 8;

    const float4* gw = reinterpret_cast<const float4*>(g_wm);
#pragma unroll
    for (int i = 0; i < 4; ++i) {
        const int idx4 = tid + i * 256;            // 0..1023
        const int rr = idx4 >> 4, cc = (idx4 & 15) << 2;
        *reinterpret_cast<float4*>(&Wm[rr][cc]) = gw[idx4];
    }
    if (tid < 64) bs[tid] = g_bias[tid];
    __syncthreads();

    // hoist A fragments: 8 k-steps x 2 m-tiles x 4 regs = 64 regs
    uint32_t af[8][2][4];
#pragma unroll
    for (int kk = 0; kk < 8; ++kk) {
        const int k0 = kk * 8;
#pragma unroll
        for (int mt = 0; mt < 2; ++mt) {
            const int rm = rb + mt * 16;
            af[kk][mt][0] = __float_as_uint(Wm[rm + la2][k0 + la3]);
            af[kk][mt][1] = __float_as_uint(Wm[rm + 8 + la2][k0 + la3]);
            af[kk][mt][2] = __float_as_uint(Wm[rm + la2][k0 + 4 + la3]);
            af[kk][mt][3] = __float_as_uint(Wm[rm + 8 + la2][k0 + 4 + la3]);
        }
    }
    const int r0 = rb + la2;
    const float bv[4] = {bs[r0], bs[r0 + 8], bs[r0 + 16], bs[r0 + 24]};

    const int tile0 = blockIdx.x * TPA;
    tile_issue(X, tile0 + 0, stages + 0 * 64 * GS, tid);
    tile_issue(X, tile0 + 1, stages + 1 * 64 * GS, tid);

#pragma unroll 1
    for (int t = 0; t < TPA; ++t) {
        cp_wait1();
        __syncthreads();
        if (t + 2 < TPA) tile_issue(X, tile0 + t + 2, stages + ((t + 2) % 3) * 64 * GS, tid);
        else cp_commit();

        const float* S = stages + (t % 3) * 64 * GS;

        float acc[2][4];
#pragma unroll
        for (int i = 0; i < 2; ++i)
#pragma unroll
            for (int j = 0; j < 4; ++j) acc[i][j] = 0.f;

#pragma unroll
        for (int kk = 0; kk < 8; ++kk) {
            const int k0 = kk * 8;
            const uint32_t b0 = ldf(S + (k0 + la3) * GS + cbw + la2);
            const uint32_t b1 = ldf(S + (k0 + 4 + la3) * GS + cbw + la2);
            mma_tf32(acc[0], af[kk][0][0], af[kk][0][1], af[kk][0][2], af[kk][0][3], b0, b1);
            mma_tf32(acc[1], af[kk][1][0], af[kk][1][1], af[kk][1][2], af[kk][1][3], b0, b1);
        }

        const int tile = tile0 + t;
        const int n = tile / PTILES;
        const int s0 = (tile - n * PTILES) * 32;
        const int c0 = cbw + la3 * 2;
#pragma unroll
        for (int mt = 0; mt < 2; ++mt) {
            const int rA = r0 + mt * 16, rB = rA + 8;
            *reinterpret_cast<float2*>(Y + (size_t)(n * C64 + rA) * HW + s0 + c0) =
                make_float2(acc[mt][0] - bv[mt * 2], acc[mt][1] - bv[mt * 2]);
            *reinterpret_cast<float2*>(Y + (size_t)(n * C64 + rB) * HW + s0 + c0) =
                make_float2(acc[mt][2] - bv[mt * 2 + 1], acc[mt][3] - bv[mt * 2 + 1]);
        }
        __syncthreads();
    }
}

// =====================================================================
extern "C" void kernel_launch(void* const* d_in, const int* in_sizes, int n_in,
                              void* d_out, int out_size) {
    const float* X = (const float*)d_in[0];
    float* Y = (float*)d_out;

    const int apply_smem = (4352 + 3 * 64 * GS + 64) * (int)sizeof(float);
    cudaFuncSetAttribute(apply_kernel, cudaFuncAttributeMaxDynamicSharedMemorySize, apply_smem);
    cudaFuncSetAttribute(solve_kernel, cudaFuncAttributeMaxDynamicSharedMemorySize,
                         4 * 64 * 68 * (int)sizeof(float));

    gram_kernel<<<NBG, 192>>>(X);
    reduce_kernel<<<129, 128>>>();
    solve_kernel<<<1, 256, 4 * 64 * 68 * sizeof(float)>>>();
    apply_kernel<<<NBA, 256, apply_smem>>>(X, Y);
}

// round 17
// speedup vs baseline: 1.0259x; 1.0259x over previous
#include <cuda_runtime.h>
#include <stdint.h>
#include <math.h>

#define C64 64
#define HW  3136
#define MTOT 401408            // 128*3136
#define PTILES 98              // 3136/32 position tiles per image
#define NBG 392
#define NPG 784                // 2 partials per gram block (split-K teams)
#define TPG 32                 // 392*32 = 12544 tiles
#define NBA 1568
#define TPA 8
#define NS_ITERS 3
#define EPSV 1e-3f
#define GS 36                  // smem tile stride in floats (144B rows)

// -------- device scratch (no allocations allowed) --------
__device__ float g_partG[NPG][C64 * C64];
__device__ float g_partS[NBG][C64];
__device__ float g_G[C64 * C64];
__device__ float g_S[C64];
__device__ float g_wm[C64 * C64];
__device__ float g_bias[C64];

// =============================== helpers ===============================
__device__ __forceinline__ void cpasync16(uint32_t dst, const void* src) {
    asm volatile("cp.async.cg.shared.global [%0], [%1], 16;" :: "r"(dst), "l"(src));
}
__device__ __forceinline__ void cp_commit() {
    asm volatile("cp.async.commit_group;" ::: "memory");
}
__device__ __forceinline__ void cp_wait1() {
    asm volatile("cp.async.wait_group 1;" ::: "memory");
}
__device__ __forceinline__ void cp_wait2() {
    asm volatile("cp.async.wait_group 2;" ::: "memory");
}

// m16n8k8 tf32 HMMA (sm_80+ feature, works on bare sm_103 target).
__device__ __forceinline__ void mma_tf32(float* c, uint32_t a0, uint32_t a1,
                                         uint32_t a2, uint32_t a3,
                                         uint32_t b0, uint32_t b1) {
    asm volatile("mma.sync.aligned.m16n8k8.row.col.f32.tf32.tf32.f32 "
                 "{%0,%1,%2,%3}, {%4,%5,%6,%7}, {%8,%9}, {%0,%1,%2,%3};"
                 : "+f"(c[0]), "+f"(c[1]), "+f"(c[2]), "+f"(c[3])
                 : "r"(a0), "r"(a1), "r"(a2), "r"(a3), "r"(b0), "r"(b1));
}
__device__ __forceinline__ uint32_t ldf(const float* p) {
    return __float_as_uint(*p);
}

// 256-thread tile loader (apply): 64 rows x 32 f32 into [64][GS].
__device__ __forceinline__ void tile_issue(const float* __restrict__ X, int tile,
                                           float* stage, int tid) {
    const int n = tile / PTILES;
    const int s0 = (tile - n * PTILES) * 32;
    const float* base = X + (size_t)n * (C64 * HW) + s0;
    const uint32_t sa = (uint32_t)__cvta_generic_to_shared(stage);
#pragma unroll
    for (int j = 0; j < 2; ++j) {
        const int idx = tid + j * 256;
        const int r = idx >> 3, q = idx & 7;
        cpasync16(sa + (uint32_t)(r * GS * 4 + q * 16), base + (size_t)r * HW + 4 * q);
    }
    cp_commit();
}

// 192-thread tile loader (gram): 512 f4 over 3 guarded rounds.
__device__ __forceinline__ void tile_issue192(const float* __restrict__ X, int tile,
                                              float* stage, int tid) {
    const int n = tile / PTILES;
    const int s0 = (tile - n * PTILES) * 32;
    const float* base = X + (size_t)n * (C64 * HW) + s0;
    const uint32_t sa = (uint32_t)__cvta_generic_to_shared(stage);
#pragma unroll
    for (int j = 0; j < 3; ++j) {
        const int idx = tid + j * 192;
        if (idx < 512) {
            const int r = idx >> 3, q = idx & 7;
            cpasync16(sa + (uint32_t)(r * GS * 4 + q * 16), base + (size_t)r * HW + 4 * q);
        }
    }
    cp_commit();
}

// =====================================================================
// Pass 1: tf32 HMMA Gram. 192 thr / 6 warps = 2 K-half teams x 3 tiles.
// Tiles per team: tw0 (0,0) diag, tw1 (32,32) diag, tw2 (32,0) offdiag
// (+ transposed mirror). 32x32 warp tiles: 8 MMAs per kk on 8 B-LDS;
// diagonal tiles reuse B fragments as A (1.0 LDS/MMA).
// Team j handles kk in {2j, 2j+1}; partial -> g_partG[2*block+j].
// 4-stage cp.async, prefetch after MMA, one barrier/tile (R11-proven).
// =====================================================================
__global__ void __launch_bounds__(192) gram_kernel(const float* __restrict__ X) {
    __shared__ float stg[4][64 * GS];
    __shared__ float ssc[3][64];

    const int tid = threadIdx.x;
    const int wid = tid >> 5, lane = tid & 31;
    const int la2 = lane >> 2, la3 = lane & 3;
    const int team = wid / 3;              // K-half
    const int tw = wid - team * 3;         // 0..2
    const int rb = (tw == 0) ? 0 : 32;
    const int cb = (tw == 1) ? 32 : 0;
    const int kbase = team * 2;
    const int sch = tid & 63, seg = tid >> 6;       // seg 0..2
    const int nf4 = (seg == 2) ? 2 : 3;
    const int f4b = seg * 3;

    float acc[2][4][4];
#pragma unroll
    for (int m = 0; m < 2; ++m)
#pragma unroll
        for (int i = 0; i < 4; ++i)
#pragma unroll
            for (int j = 0; j < 4; ++j) acc[m][i][j] = 0.f;
    float ssum = 0.f;

    const int tile0 = blockIdx.x * TPG;
    tile_issue192(X, tile0 + 0, stg[0], tid);
    tile_issue192(X, tile0 + 1, stg[1], tid);
    tile_issue192(X, tile0 + 2, stg[2], tid);

#pragma unroll 1
    for (int t = 0; t < TPG; ++t) {
        const float* S = stg[t & 3];
        cp_wait2();
        __syncthreads();

        // channel sums: thread covers (ch, float4-range)
#pragma unroll
        for (int j = 0; j < 3; ++j) {
            if (j < nf4) {
                const float4 u = *reinterpret_cast<const float4*>(S + sch * GS + (f4b + j) * 4);
                ssum += (u.x + u.y) + (u.z + u.w);
            }
        }

#pragma unroll
        for (int kk2 = 0; kk2 < 2; ++kk2) {
            const int k0 = (kbase + kk2) * 8;
            uint32_t B0[4], B1[4];
#pragma unroll
            for (int nt = 0; nt < 4; ++nt) {
                B0[nt] = ldf(S + (cb + nt * 8 + la2) * GS + k0 + la3);
                B1[nt] = ldf(S + (cb + nt * 8 + la2) * GS + k0 + 4 + la3);
            }
            uint32_t A[2][4];
            if (tw == 2) {   // offdiag: load A rows 32..63 separately
#pragma unroll
                for (int mt = 0; mt < 2; ++mt) {
                    const int rm = rb + mt * 16;
                    A[mt][0] = ldf(S + (rm + la2) * GS + k0 + la3);
                    A[mt][1] = ldf(S + (rm + 8 + la2) * GS + k0 + la3);
                    A[mt][2] = ldf(S + (rm + la2) * GS + k0 + 4 + la3);
                    A[mt][3] = ldf(S + (rm + 8 + la2) * GS + k0 + 4 + la3);
                }
            } else {         // diag: A fragments == B fragments
#pragma unroll
                for (int mt = 0; mt < 2; ++mt) {
                    A[mt][0] = B0[2 * mt];
                    A[mt][1] = B0[2 * mt + 1];
                    A[mt][2] = B1[2 * mt];
                    A[mt][3] = B1[2 * mt + 1];
                }
            }
#pragma unroll
            for (int mt = 0; mt < 2; ++mt)
#pragma unroll
                for (int nt = 0; nt < 4; ++nt)
                    mma_tf32(acc[mt][nt], A[mt][0], A[mt][1], A[mt][2], A[mt][3],
                             B0[nt], B1[nt]);
        }

        if (t + 3 < TPG) tile_issue192(X, tile0 + t + 3, stg[(t + 3) & 3], tid);
        else cp_commit();   // keep group accounting consistent
    }

    // write partial G (own 32x32 block + mirror for offdiag warp)
    float* pg = g_partG[blockIdx.x * 2 + team];
#pragma unroll
    for (int mt = 0; mt < 2; ++mt) {
        const int r0 = rb + mt * 16 + la2;
#pragma unroll
        for (int nt = 0; nt < 4; ++nt) {
            const int c0 = cb + nt * 8 + la3 * 2;
            *reinterpret_cast<float2*>(pg + r0 * C64 + c0) =
                make_float2(acc[mt][nt][0], acc[mt][nt][1]);
            *reinterpret_cast<float2*>(pg + (r0 + 8) * C64 + c0) =
                make_float2(acc[mt][nt][2], acc[mt][nt][3]);
            if (tw == 2) {
                pg[c0 * C64 + r0] = acc[mt][nt][0];
                pg[(c0 + 1) * C64 + r0] = acc[mt][nt][1];
                pg[c0 * C64 + r0 + 8] = acc[mt][nt][2];
                pg[(c0 + 1) * C64 + r0 + 8] = acc[mt][nt][3];
            }
        }
    }
    // reduce channel sums
    ssc[seg][sch] = ssum;
    __syncthreads();
    if (tid < 64)
        g_partS[blockIdx.x][tid] = ssc[0][tid] + ssc[1][tid] + ssc[2][tid];
}

// =====================================================================
// Pass 1.5: reduce partials (fixed order -> deterministic)
// =====================================================================
__global__ void __launch_bounds__(128) reduce_kernel() {
    const int tid = threadIdx.x;
    if (blockIdx.x < 128) {
        __shared__ float4 s[8][8];
        if (tid < 64) {
            const int lane = tid & 7, g = tid >> 3;
            const int e4 = blockIdx.x * 8 + lane;
            const float4* pg = reinterpret_cast<const float4*>(g_partG);
            float4 a = make_float4(0.f, 0.f, 0.f, 0.f);
            const int b0 = g * (NPG / 8);
#pragma unroll 7
            for (int b = 0; b < NPG / 8; ++b) {
                const float4 t = pg[(size_t)(b0 + b) * 1024 + e4];
                a.x += t.x; a.y += t.y; a.z += t.z; a.w += t.w;
            }
            s[g][lane] = a;
        }
        __syncthreads();
        if (tid < 8) {
            float4 r = make_float4(0.f, 0.f, 0.f, 0.f);
            for (int i = 0; i < 8; ++i) {
                const float4 t = s[i][tid];
                r.x += t.x; r.y += t.y; r.z += t.z; r.w += t.w;
            }
            reinterpret_cast<float4*>(g_G)[blockIdx.x * 8 + tid] = r;
        }
    } else {
        __shared__ float s2[2][64];
        const int ch = tid & 63, half = tid >> 6;
        float a = 0.f;
        const int b0 = half * (NBG / 2);
#pragma unroll 4
        for (int b = 0; b < NBG / 2; ++b) a += g_partS[b0 + b][ch];
        s2[half][ch] = a;
        __syncthreads();
        if (tid < 64) g_S[tid] = s2[0][tid] + s2[1][tid];
    }
}

// =====================================================================
// Pass 2: single-block Newton-Schulz inverse sqrt (fp32, FFMA2), 256 thr
// =====================================================================
__device__ __forceinline__ uint64_t pack2(float v) {
    uint64_t r; asm("mov.b64 %0, {%1, %1};" : "=l"(r) : "f"(v)); return r;
}
__device__ __forceinline__ void ffma2(uint64_t& d, uint64_t a, uint64_t b) {
    asm("fma.rn.f32x2 %0, %1, %2, %0;" : "+l"(d) : "l"(a), "l"(b));
}
__device__ __forceinline__ float2 unpack2(uint64_t v) {
    float2 f; asm("mov.b64 {%0, %1}, %2;" : "=f"(f.x), "=f"(f.y) : "l"(v)); return f;
}

__device__ __forceinline__ void mm64_2(const float (*P)[68], const float (*Q)[68],
                                       float (*Cm)[68], int ty, int tx) {
    uint64_t acc[2][4];
#pragma unroll
    for (int i = 0; i < 2; ++i)
#pragma unroll
        for (int j = 0; j < 4; ++j) acc[i][j] = 0ull;
#pragma unroll 8
    for (int k = 0; k < 64; ++k) {
        const ulonglong2 a = *reinterpret_cast<const ulonglong2*>(&P[k][ty * 4]);
        const float4 b = *reinterpret_cast<const float4*>(&Q[k][tx * 4]);
        const uint64_t bd[4] = {pack2(b.x), pack2(b.y), pack2(b.z), pack2(b.w)};
#pragma unroll
        for (int j = 0; j < 4; ++j) { ffma2(acc[0][j], a.x, bd[j]); ffma2(acc[1][j], a.y, bd[j]); }
    }
#pragma unroll
    for (int i = 0; i < 2; ++i) {
        const float2 u0 = unpack2(acc[i][0]), u1 = unpack2(acc[i][1]);
        const float2 u2 = unpack2(acc[i][2]), u3 = unpack2(acc[i][3]);
        const int rowA = ty * 4 + 2 * i, rowB = rowA + 1;
        Cm[rowA][tx * 4 + 0] = u0.x; Cm[rowA][tx * 4 + 1] = u1.x;
        Cm[rowA][tx * 4 + 2] = u2.x; Cm[rowA][tx * 4 + 3] = u3.x;
        Cm[rowB][tx * 4 + 0] = u0.y; Cm[rowB][tx * 4 + 1] = u1.y;
        Cm[rowB][tx * 4 + 2] = u2.y; Cm[rowB][tx * 4 + 3] = u3.y;
    }
}

__global__ void __launch_bounds__(256) solve_kernel() {
    extern __shared__ float smf[];
    float (*An)[68] = (float(*)[68])smf;
    float (*Z)[68]  = (float(*)[68])(smf + 1 * 64 * 68);
    float (*B1)[68] = (float(*)[68])(smf + 2 * 64 * 68);
    float (*B2)[68] = (float(*)[68])(smf + 3 * 64 * 68);
    __shared__ float rowsum[64];
    __shared__ float rinv;

    const int tid = threadIdx.x;
    const int ty = tid >> 4, tx = tid & 15;
    const float invm = 1.f / (float)MTOT;

    for (int e = tid; e < 4096; e += 256) {
        const int i = e >> 6, j = e & 63;
        float s = g_G[e] * invm - (g_S[i] * invm) * (g_S[j] * invm);
        if (i == j) s += EPSV;
        An[i][j] = s;
        Z[i][j] = (i == j) ? 1.f : 0.f;
    }
    __syncthreads();
    if (tid < 64) {
        float rs = 0.f;
        for (int j = 0; j < 64; ++j) rs += fabsf(An[tid][j]);
        rowsum[tid] = rs;
    }
    __syncthreads();
    if (tid == 0) {
        float mx = 0.f;
        for (int i = 0; i < 64; ++i) mx = fmaxf(mx, rowsum[i]);
        rinv = 1.f / mx;
    }
    __syncthreads();
    const float r = rinv;
    for (int e = tid; e < 4096; e += 256) An[e >> 6][e & 63] *= r;
    __syncthreads();

    for (int it = 0; it < NS_ITERS; ++it) {
        mm64_2(Z, Z, B1, ty, tx);
        __syncthreads();
        mm64_2(B1, Z, B2, ty, tx);
        __syncthreads();
        {
            uint64_t acc[2][4];
#pragma unroll
            for (int i = 0; i < 2; ++i)
#pragma unroll
                for (int j = 0; j < 4; ++j) acc[i][j] = 0ull;
#pragma unroll 8
            for (int k = 0; k < 64; ++k) {
                const ulonglong2 a = *reinterpret_cast<const ulonglong2*>(&An[k][ty * 4]);
                const float4 b = *reinterpret_cast<const float4*>(&B2[k][tx * 4]);
                const uint64_t bd[4] = {pack2(b.x), pack2(b.y), pack2(b.z), pack2(b.w)};
#pragma unroll
                for (int j = 0; j < 4; ++j) { ffma2(acc[0][j], a.x, bd[j]); ffma2(acc[1][j], a.y, bd[j]); }
            }
#pragma unroll
            for (int i = 0; i < 2; ++i) {
                const float2 u[4] = {unpack2(acc[i][0]), unpack2(acc[i][1]),
                                     unpack2(acc[i][2]), unpack2(acc[i][3])};
                const int rowA = ty * 4 + 2 * i, rowB = rowA + 1;
#pragma unroll
                for (int j = 0; j < 4; ++j) {
                    Z[rowA][tx * 4 + j] = 1.5f * Z[rowA][tx * 4 + j] - 0.5f * u[j].x;
                    Z[rowB][tx * 4 + j] = 1.5f * Z[rowB][tx * 4 + j] - 0.5f * u[j].y;
                }
            }
        }
        __syncthreads();
    }

    const float sr = sqrtf(r);
    for (int e = tid; e < 4096; e += 256) g_wm[e] = Z[e >> 6][e & 63] * sr;
    __syncthreads();
    if (tid < 64) {
        float b = 0.f;
        for (int k = 0; k < 64; ++k) b += Z[tid][k] * g_S[k];
        g_bias[tid] = b * sr * invm;
    }
}

// =====================================================================
// Pass 3: tf32 HMMA apply (R14-measured 47.1us). 32x8 warp tiles,
// A fragments hoisted (64 regs); direct fragment stores.
// dyn smem: Wm[64][68] | 3 stages [64][GS] | bias[64]
// =====================================================================
__global__ void __launch_bounds__(256) apply_kernel(const float* __restrict__ X,
                                                    float* __restrict__ Y) {
    extern __shared__ float sm[];
    float (*Wm)[68] = (float(*)[68])sm;                 // 4352 floats
    float* stages = sm + 4352;                          // 3 * 2304
    float* bs = sm + 4352 + 3 * 64 * GS;

    const int tid = threadIdx.x;
    const int wid = tid >> 5, lane = tid & 31;
    const int la2 = lane >> 2, la3 = lane & 3;
    const int rb = (wid & 1) * 32, cbw = (wid >> 1) * 8;

    const float4* gw = reinterpret_cast<const float4*>(g_wm);
#pragma unroll
    for (int i = 0; i < 4; ++i) {
        const int idx4 = tid + i * 256;            // 0..1023
        const int rr = idx4 >> 4, cc = (idx4 & 15) << 2;
        *reinterpret_cast<float4*>(&Wm[rr][cc]) = gw[idx4];
    }
    if (tid < 64) bs[tid] = g_bias[tid];
    __syncthreads();

    // hoist A fragments: 8 k-steps x 2 m-tiles x 4 regs = 64 regs
    uint32_t af[8][2][4];
#pragma unroll
    for (int kk = 0; kk < 8; ++kk) {
        const int k0 = kk * 8;
#pragma unroll
        for (int mt = 0; mt < 2; ++mt) {
            const int rm = rb + mt * 16;
            af[kk][mt][0] = __float_as_uint(Wm[rm + la2][k0 + la3]);
            af[kk][mt][1] = __float_as_uint(Wm[rm + 8 + la2][k0 + la3]);
            af[kk][mt][2] = __float_as_uint(Wm[rm + la2][k0 + 4 + la3]);
            af[kk][mt][3] = __float_as_uint(Wm[rm + 8 + la2][k0 + 4 + la3]);
        }
    }
    const int r0 = rb + la2;
    const float bv[4] = {bs[r0], bs[r0 + 8], bs[r0 + 16], bs[r0 + 24]};

    const int tile0 = blockIdx.x * TPA;
    tile_issue(X, tile0 + 0, stages + 0 * 64 * GS, tid);
    tile_issue(X, tile0 + 1, stages + 1 * 64 * GS, tid);

#pragma unroll 1
    for (int t = 0; t < TPA; ++t) {
        cp_wait1();
        __syncthreads();
        if (t + 2 < TPA) tile_issue(X, tile0 + t + 2, stages + ((t + 2) % 3) * 64 * GS, tid);
        else cp_commit();

        const float* S = stages + (t % 3) * 64 * GS;

        float acc[2][4];
#pragma unroll
        for (int i = 0; i < 2; ++i)
#pragma unroll
            for (int j = 0; j < 4; ++j) acc[i][j] = 0.f;

#pragma unroll
        for (int kk = 0; kk < 8; ++kk) {
            const int k0 = kk * 8;
            const uint32_t b0 = ldf(S + (k0 + la3) * GS + cbw + la2);
            const uint32_t b1 = ldf(S + (k0 + 4 + la3) * GS + cbw + la2);
            mma_tf32(acc[0], af[kk][0][0], af[kk][0][1], af[kk][0][2], af[kk][0][3], b0, b1);
            mma_tf32(acc[1], af[kk][1][0], af[kk][1][1], af[kk][1][2], af[kk][1][3], b0, b1);
        }

        const int tile = tile0 + t;
        const int n = tile / PTILES;
        const int s0 = (tile - n * PTILES) * 32;
        const int c0 = cbw + la3 * 2;
#pragma unroll
        for (int mt = 0; mt < 2; ++mt) {
            const int rA = r0 + mt * 16, rB = rA + 8;
            *reinterpret_cast<float2*>(Y + (size_t)(n * C64 + rA) * HW + s0 + c0) =
                make_float2(acc[mt][0] - bv[mt * 2], acc[mt][1] - bv[mt * 2]);
            *reinterpret_cast<float2*>(Y + (size_t)(n * C64 + rB) * HW + s0 + c0) =
                make_float2(acc[mt][2] - bv[mt * 2 + 1], acc[mt][3] - bv[mt * 2 + 1]);
        }
        __syncthreads();
    }
}

// =====================================================================
extern "C" void kernel_launch(void* const* d_in, const int* in_sizes, int n_in,
                              void* d_out, int out_size) {
    const float* X = (const float*)d_in[0];
    float* Y = (float*)d_out;

    const int apply_smem = (4352 + 3 * 64 * GS + 64) * (int)sizeof(float);
    cudaFuncSetAttribute(apply_kernel, cudaFuncAttributeMaxDynamicSharedMemorySize, apply_smem);
    cudaFuncSetAttribute(solve_kernel, cudaFuncAttributeMaxDynamicSharedMemorySize,
                         4 * 64 * 68 * (int)sizeof(float));

    gram_kernel<<<NBG, 192>>>(X);
    reduce_kernel<<<129, 128>>>();
    solve_kernel<<<1, 256, 4 * 64 * 68 * sizeof(float)>>>();
    apply_kernel<<<NBA, 256, apply_smem>>>(X, Y);
}